// round 12
// baseline (speedup 1.0000x reference)
#include <cuda_runtime.h>

#define NS 4096
#define NBATCH 32
#define TPB 256
#define SROW 17      // smem row stride in floats (16 feats + 1 pad)

// pywt db4 dec filters, time-reversed (cross-correlation form)
__device__ __constant__ float cH0[8] = {
     0.23037781330885523f,  0.7148465705525415f,   0.6308807679295904f,
    -0.02798376941698385f, -0.18703481171888114f,  0.030841381835986965f,
     0.032883011666982945f, -0.010597401784997278f };
__device__ __constant__ float cH1[8] = {
    -0.010597401784997278f, -0.032883011666982945f, 0.030841381835986965f,
     0.18703481171888114f,  -0.02798376941698385f,  -0.6308807679295904f,
     0.7148465705525415f,   -0.23037781330885523f };

// Lowpass scratch planes, (B, T_k, 64) contiguous. lo1 not needed in gmem.
__device__ float g_scratch[8126464];
#define OFF_LO2 4194304
#define OFF_LO3 6291456
#define OFF_LO4 7340032
#define OFF_LO5 7864320

// window sizes (rows) for the in-smem cascade, derived from receptive fields
#define W1 602   // lo1 window: [O1-45,  O1+557)
#define W2 298   // lo2 window: [O2-21,  O2+277)
#define W3 146   // lo3 window: [O3-9,   O3+137)
#define W4 70    // lo4 window: [O4-3,   O4+67)

__device__ __forceinline__ int level_of(float sc) {
    int l = 2 + (int)rintf(sc * 3.0f);          // round-half-even, matches jnp.round
    return l < 2 ? 2 : (l > 5 ? 5 : l);
}

// one smem->smem analysis level over a window; writes owned rows to gmem
__device__ __forceinline__ void level_smem(
    const float* __restrict__ sIn, int baseIn,
    float* __restrict__ sOut, int baseOut, int Win, int Tout,
    int Oown, int Cown,
    float4* __restrict__ detPlane,          // plane base with batch applied
    float4* __restrict__ loScratch,         // scratch base with batch applied (or null)
    int fg, int det_idx, const float* __restrict__ scores)
{
    for (int i = threadIdx.x; i < Win * 4; i += TPB) {
        const int nl = i >> 2, c = i & 3;
        const int n = baseOut + nl;
        float4 lo = make_float4(0.f, 0.f, 0.f, 0.f);
        float4 hi = make_float4(0.f, 0.f, 0.f, 0.f);
        if (n >= 0 && n < Tout) {
#pragma unroll
            for (int t = 0; t < 8; ++t) {
                int r = 2 * n + t - 3;            // guaranteed within input window
                const float* p = sIn + (r - baseIn) * SROW + c * 4;
                float c0 = cH0[t], c1 = cH1[t];
                lo.x = fmaf(c0, p[0], lo.x); lo.y = fmaf(c0, p[1], lo.y);
                lo.z = fmaf(c0, p[2], lo.z); lo.w = fmaf(c0, p[3], lo.w);
                hi.x = fmaf(c1, p[0], hi.x); hi.y = fmaf(c1, p[1], hi.y);
                hi.z = fmaf(c1, p[2], hi.z); hi.w = fmaf(c1, p[3], hi.w);
            }
        }
        if (sOut) {
            float* q = sOut + nl * SROW + c * 4;
            q[0] = lo.x; q[1] = lo.y; q[2] = lo.z; q[3] = lo.w;
        }
        if (n >= Oown && n < Oown + Cown) {
            float4 m = hi;
            if (det_idx >= 2) {                   // det 0,1 always active (lf>=2)
                const int f = fg * 16 + c * 4;
                if (det_idx >= level_of(__ldg(scores + f + 0))) m.x = 0.f;
                if (det_idx >= level_of(__ldg(scores + f + 1))) m.y = 0.f;
                if (det_idx >= level_of(__ldg(scores + f + 2))) m.z = 0.f;
                if (det_idx >= level_of(__ldg(scores + f + 3))) m.w = 0.f;
            }
            detPlane[(size_t)n * 16 + fg * 4 + c] = m;
            if (loScratch) loScratch[(size_t)n * 16 + fg * 4 + c] = lo;
        }
    }
}

// ---------------- fused 5-level cascade, one CTA = (b, s-tile, 16-feat group) ----------------
__global__ void __launch_bounds__(TPB)
fused_cascade(const float* __restrict__ x, float* __restrict__ out,
              const float* __restrict__ scores)
{
    extern __shared__ float sm[];
    float* s1 = sm;
    float* s2 = s1 + W1 * SROW;
    float* s3 = s2 + W2 * SROW;
    float* s4 = s3 + W3 * SROW;

    const int b  = blockIdx.x >> 4;
    const int t  = (blockIdx.x >> 2) & 3;       // s-tile 0..3
    const int fg = blockIdx.x & 3;              // feature group of 16
    const int tid = threadIdx.x;

    const int O1 = 512 * t, O2 = 256 * t, O3 = 128 * t, O4 = 64 * t, O5 = 32 * t;
    const int base1 = O1 - 45, base2 = O2 - 21, base3 = O3 - 9, base4 = O4 - 3;

    const size_t PLANE4 = (size_t)NBATCH * NS * 16;
    float4* outb = (float4*)out + (size_t)b * NS * 16;     // batch-applied, plane 0

    // ---- level 1: gmem x -> s1 window, det1 owned rows ----
    {
        const float4* xb = (const float4*)x + (size_t)b * NS * 16 + fg * 4;
        float4* det1 = outb + 1 * PLANE4;
        for (int i = tid; i < W1 * 4; i += TPB) {
            const int nl = i >> 2, c = i & 3;
            const int n = base1 + nl;
            float4 lo = make_float4(0.f, 0.f, 0.f, 0.f);
            float4 hi = make_float4(0.f, 0.f, 0.f, 0.f);
            if (n >= 0 && n < 2048) {
#pragma unroll
                for (int tt = 0; tt < 8; ++tt) {
                    int r = 2 * n + tt - 3;
                    if (r >= 0 && r < NS) {
                        float4 v = __ldg(xb + (size_t)r * 16 + c);
                        float c0 = cH0[tt], c1 = cH1[tt];
                        lo.x = fmaf(c0, v.x, lo.x); lo.y = fmaf(c0, v.y, lo.y);
                        lo.z = fmaf(c0, v.z, lo.z); lo.w = fmaf(c0, v.w, lo.w);
                        hi.x = fmaf(c1, v.x, hi.x); hi.y = fmaf(c1, v.y, hi.y);
                        hi.z = fmaf(c1, v.z, hi.z); hi.w = fmaf(c1, v.w, hi.w);
                    }
                }
            }
            float* q = s1 + nl * SROW + c * 4;
            q[0] = lo.x; q[1] = lo.y; q[2] = lo.z; q[3] = lo.w;
            if (n >= O1 && n < O1 + 512)
                det1[(size_t)n * 16 + fg * 4 + c] = hi;
        }
    }
    __syncthreads();

    float4* scr2 = (float4*)(g_scratch + OFF_LO2) + (size_t)b * 1024 * 16;
    float4* scr3 = (float4*)(g_scratch + OFF_LO3) + (size_t)b *  512 * 16;
    float4* scr4 = (float4*)(g_scratch + OFF_LO4) + (size_t)b *  256 * 16;
    float4* scr5 = (float4*)(g_scratch + OFF_LO5) + (size_t)b *  128 * 16;

    // ---- level 2 ----
    level_smem(s1, base1, s2, base2, W2, 1024, O2, 256,
               outb + 2 * PLANE4, scr2, fg, 1, scores);
    __syncthreads();
    // ---- level 3 ----
    level_smem(s2, base2, s3, base3, W3, 512, O3, 128,
               outb + 3 * PLANE4, scr3, fg, 2, scores);
    __syncthreads();
    // ---- level 4 ----
    level_smem(s3, base3, s4, base4, W4, 256, O4, 64,
               outb + 4 * PLANE4, scr4, fg, 3, scores);
    __syncthreads();
    // ---- level 5 (no smem out) ----
    level_smem(s4, base4, (float*)0, O5, 32, 128, O5, 32,
               outb + 5 * PLANE4, scr5, fg, 4, scores);

    // ---- tail zeros: this CTA's share of each det plane's tail ----
    // per-plane tail sizes/4: k1:512 k2:768 k3:896 k4:960 k5:992 (sum 4128 rows)
    const float4 z = make_float4(0.f, 0.f, 0.f, 0.f);
    for (int i = tid; i < 4128; i += TPB) {
        int k, T, Z, rel;
        if      (i <  512) { k = 1; T = 2048; Z = 512; rel = i;        }
        else if (i < 1280) { k = 2; T = 1024; Z = 768; rel = i - 512;  }
        else if (i < 2176) { k = 3; T =  512; Z = 896; rel = i - 1280; }
        else if (i < 3136) { k = 4; T =  256; Z = 960; rel = i - 2176; }
        else               { k = 5; T =  128; Z = 992; rel = i - 3136; }
        int row = T + Z * t + rel;
        float4* p = outb + (size_t)k * PLANE4 + (size_t)row * 16 + fg * 4;
        p[0] = z; p[1] = z; p[2] = z; p[3] = z;
    }
}

// ---------------- final: approx (0), high_freq (6), low_freq (7) ----------------
__global__ void __launch_bounds__(TPB)
final_kernel(float* __restrict__ out, const float* __restrict__ scores)
{
    int idx = blockIdx.x * TPB + threadIdx.x;
    const int f4 = idx & 15;
    const int s  = (idx >> 4) & (NS - 1);
    const int b  = idx >> 16;

    const size_t PLANE4 = (size_t)NBATCH * NS * 16;
    const size_t row4   = ((size_t)b * NS + s) * 16 + f4;

    // high_freq = sum of masked detail prefixes (det_k zero for s >= T_k)
    float4 h = make_float4(0.f, 0.f, 0.f, 0.f);
#pragma unroll
    for (int i = 0; i < 5; ++i) {
        if (s < (2048 >> i)) {
            float4 d = __ldg((const float4*)out + (1 + i) * PLANE4 + row4);
            h.x += d.x; h.y += d.y; h.z += d.z; h.w += d.w;
        }
    }
    ((float4*)out)[6 * PLANE4 + row4] = h;

    const size_t offs[4] = { OFF_LO2, OFF_LO3, OFF_LO4, OFF_LO5 };
    const int f = f4 * 4;
    float av[4];
#pragma unroll
    for (int j = 0; j < 4; ++j) {
        int k = level_of(__ldg(scores + f + j)) - 2;     // 0..3
        int T = 1024 >> k;
        av[j] = (s < T)
            ? __ldg(g_scratch + offs[k] + ((size_t)b * T + s) * 64 + f + j)
            : 0.f;
    }
    float4 a = make_float4(av[0], av[1], av[2], av[3]);
    ((float4*)out)[row4] = a;               // approx
    ((float4*)out)[7 * PLANE4 + row4] = a;  // low_freq
}

extern "C" void kernel_launch(void* const* d_in, const int* in_sizes, int n_in,
                              void* d_out, int out_size)
{
    const float* x      = (const float*)d_in[0];
    const float* scores = (const float*)d_in[1];
    float* out          = (float*)d_out;

    const size_t smem = (size_t)(W1 + W2 + W3 + W4) * SROW * sizeof(float);  // 75888
    cudaFuncSetAttribute(fused_cascade, cudaFuncAttributeMaxDynamicSharedMemorySize,
                         (int)smem);

    fused_cascade<<<NBATCH * 4 * 4, TPB, smem>>>(x, out, scores);
    final_kernel<<<(NBATCH * NS * 16) / TPB, TPB>>>(out, scores);
}

// round 13
// speedup vs baseline: 1.6446x; 1.6446x over previous
#include <cuda_runtime.h>

#define NS 4096
#define NBATCH 32
#define TPB 256

// pywt db4 dec filters, time-reversed (cross-correlation form)
__device__ __constant__ float cH0[8] = {
     0.23037781330885523f,  0.7148465705525415f,   0.6308807679295904f,
    -0.02798376941698385f, -0.18703481171888114f,  0.030841381835986965f,
     0.032883011666982945f, -0.010597401784997278f };
__device__ __constant__ float cH1[8] = {
    -0.010597401784997278f, -0.032883011666982945f, 0.030841381835986965f,
     0.18703481171888114f,  -0.02798376941698385f,  -0.6308807679295904f,
     0.7148465705525415f,   -0.23037781330885523f };

// Lowpass scratch planes, (B, T_k, 64) contiguous.
__device__ float g_scratch[8126464];
#define OFF_LO1 0
#define OFF_LO2 4194304
#define OFF_LO3 6291456
#define OFF_LO4 7340032
#define OFF_LO5 7864320

__device__ __forceinline__ int level_of(float sc) {
    int l = 2 + (int)rintf(sc * 3.0f);          // round-half-even, matches jnp.round
    return l < 2 ? 2 : (l > 5 ? 5 : l);
}

// One analysis level over full 64-feature rows, ONE float4 per thread (the
// proven R3 mapping). Full grid over (b, n<4096, f4): coefficient threads
// convolve, tail threads zero the detail plane.
// Interior fast path: for 2 <= n < TOUT-2 all 8 taps are in range -> 8
// unconditional LDG.128 off one base pointer (immediate offsets, MLP=8).
template <int TIN>
__global__ void __launch_bounds__(TPB)
level_kernel(const float* __restrict__ in, float* __restrict__ loOut,
             float* __restrict__ det, const float* __restrict__ scores,
             int detIdx)
{
    const int TOUT = TIN / 2;
    int idx = blockIdx.x * TPB + threadIdx.x;      // (b, n, f4)
    const int f4 = idx & 15;
    const int n  = (idx >> 4) & (NS - 1);
    const int b  = idx >> 16;                      // 4096*16 per batch

    float4* pd = (float4*)det + ((size_t)b * NS + n) * 16 + f4;
    if (n >= TOUT) {                               // zero tail of detail plane
        *pd = make_float4(0.f, 0.f, 0.f, 0.f);
        return;
    }

    const float4* pin = (const float4*)in + (size_t)b * TIN * 16 + f4;
    float4 lo = make_float4(0.f, 0.f, 0.f, 0.f);
    float4 hi = make_float4(0.f, 0.f, 0.f, 0.f);

    if (n >= 2 && n < TOUT - 2) {
        // branchless interior: base + immediate offsets, loads front-batched
        const float4* p0 = pin + (size_t)(2 * n - 3) * 16;
        float4 v[8];
#pragma unroll
        for (int t = 0; t < 8; ++t) v[t] = __ldg(p0 + t * 16);
#pragma unroll
        for (int t = 0; t < 8; ++t) {
            const float c0 = cH0[t], c1 = cH1[t];
            lo.x = fmaf(c0, v[t].x, lo.x); lo.y = fmaf(c0, v[t].y, lo.y);
            lo.z = fmaf(c0, v[t].z, lo.z); lo.w = fmaf(c0, v[t].w, lo.w);
            hi.x = fmaf(c1, v[t].x, hi.x); hi.y = fmaf(c1, v[t].y, hi.y);
            hi.z = fmaf(c1, v[t].z, hi.z); hi.w = fmaf(c1, v[t].w, hi.w);
        }
    } else {
#pragma unroll
        for (int t = 0; t < 8; ++t) {
            int r = 2 * n + t - 3;
            if (r >= 0 && r < TIN) {
                float4 v = __ldg(pin + (size_t)r * 16);
                const float c0 = cH0[t], c1 = cH1[t];
                lo.x = fmaf(c0, v.x, lo.x); lo.y = fmaf(c0, v.y, lo.y);
                lo.z = fmaf(c0, v.z, lo.z); lo.w = fmaf(c0, v.w, lo.w);
                hi.x = fmaf(c1, v.x, hi.x); hi.y = fmaf(c1, v.y, hi.y);
                hi.z = fmaf(c1, v.z, hi.z); hi.w = fmaf(c1, v.w, hi.w);
            }
        }
    }

    // per-feature activity mask: detail i populated iff i < lf (lf >= 2)
    if (detIdx >= 2) {
        const int f = f4 * 4;
        if (detIdx >= level_of(__ldg(scores + f + 0))) hi.x = 0.f;
        if (detIdx >= level_of(__ldg(scores + f + 1))) hi.y = 0.f;
        if (detIdx >= level_of(__ldg(scores + f + 2))) hi.z = 0.f;
        if (detIdx >= level_of(__ldg(scores + f + 3))) hi.w = 0.f;
    }

    ((float4*)loOut)[((size_t)b * TOUT + n) * 16 + f4] = lo;
    *pd = hi;
}

// Final: approx (plane 0), high_freq (plane 6), low_freq (plane 7).
__global__ void __launch_bounds__(TPB)
final_kernel(float* __restrict__ out, const float* __restrict__ scores)
{
    int idx = blockIdx.x * TPB + threadIdx.x;
    const int f4 = idx & 15;
    const int s  = (idx >> 4) & (NS - 1);
    const int b  = idx >> 16;

    const size_t PLANE4 = (size_t)NBATCH * NS * 16;      // float4 units
    const size_t row4   = ((size_t)b * NS + s) * 16 + f4;

    // high_freq = sum of masked detail prefixes (det_k zero for s >= T_k)
    float4 h = make_float4(0.f, 0.f, 0.f, 0.f);
#pragma unroll
    for (int i = 0; i < 5; ++i) {
        if (s < (2048 >> i)) {
            float4 d = __ldg((const float4*)out + (1 + i) * PLANE4 + row4);
            h.x += d.x; h.y += d.y; h.z += d.z; h.w += d.w;
        }
    }
    ((float4*)out)[6 * PLANE4 + row4] = h;

    // approx: per-feature selected lowpass level
    const size_t offs[4] = { OFF_LO2, OFF_LO3, OFF_LO4, OFF_LO5 };
    const int f = f4 * 4;
    float av[4];
#pragma unroll
    for (int j = 0; j < 4; ++j) {
        int k = level_of(__ldg(scores + f + j)) - 2;     // 0..3
        int T = 1024 >> k;
        av[j] = (s < T)
            ? __ldg(g_scratch + offs[k] + ((size_t)b * T + s) * 64 + f + j)
            : 0.f;
    }
    float4 a = make_float4(av[0], av[1], av[2], av[3]);
    ((float4*)out)[row4] = a;               // approx
    ((float4*)out)[7 * PLANE4 + row4] = a;  // low_freq
}

extern "C" void kernel_launch(void* const* d_in, const int* in_sizes, int n_in,
                              void* d_out, int out_size)
{
    const float* x      = (const float*)d_in[0];
    const float* scores = (const float*)d_in[1];
    float* out          = (float*)d_out;

    float* scratch;
    cudaGetSymbolAddress((void**)&scratch, g_scratch);
    float* lo1 = scratch + OFF_LO1;
    float* lo2 = scratch + OFF_LO2;
    float* lo3 = scratch + OFF_LO3;
    float* lo4 = scratch + OFF_LO4;
    float* lo5 = scratch + OFF_LO5;

    const size_t PLANE = (size_t)NBATCH * NS * 64;
    const int grid = (NBATCH * NS * 16) / TPB;          // 8192 blocks

    level_kernel<4096><<<grid, TPB>>>(x,   lo1, out + 1 * PLANE, scores, 0);
    level_kernel<2048><<<grid, TPB>>>(lo1, lo2, out + 2 * PLANE, scores, 1);
    level_kernel<1024><<<grid, TPB>>>(lo2, lo3, out + 3 * PLANE, scores, 2);
    level_kernel< 512><<<grid, TPB>>>(lo3, lo4, out + 4 * PLANE, scores, 3);
    level_kernel< 256><<<grid, TPB>>>(lo4, lo5, out + 5 * PLANE, scores, 4);
    final_kernel<<<grid, TPB>>>(out, scores);
}